// round 5
// baseline (speedup 1.0000x reference)
#include <cuda_runtime.h>
#include <math.h>
#include <string.h>

#define B_ 512
#define T_ 512
#define I_ 256
#define H_ 250

// ---------------------------------------------------------------------------
// packed fp32x2 helpers (Blackwell dual fp32 pipe; ptxas never auto-emits)
// ---------------------------------------------------------------------------
__device__ __forceinline__ unsigned long long fma2(unsigned long long a,
                                                   unsigned long long b,
                                                   unsigned long long c) {
    unsigned long long d;
    asm("fma.rn.f32x2 %0, %1, %2, %3;" : "=l"(d) : "l"(a), "l"(b), "l"(c));
    return d;
}
__device__ __forceinline__ float2 u2f2(unsigned long long u) {
    float2 f; memcpy(&f, &u, 8); return f;
}
__device__ __forceinline__ unsigned int smem_u32(const void* p) {
    unsigned int a;
    asm("{ .reg .u64 t; cvta.to.shared.u64 t, %1; cvt.u32.u64 %0, t; }"
        : "=r"(a) : "l"(p));
    return a;
}

// ---------------------------------------------------------------------------
// Kernel 1: xproj GEMM  out[m, n] = sum_k x[m,k] * Wx[n,k] + bh[n]
//   (unchanged from round 4)
// ---------------------------------------------------------------------------
#define BM 128
#define BN 64
#define BK 32
#define TSTRA 36

__global__ __launch_bounds__(256, 2) void xproj_kernel(
    const float* __restrict__ x, const float* __restrict__ Wx,
    const float* __restrict__ bh, float* __restrict__ out)
{
    __shared__ float As[BM][TSTRA];
    __shared__ float Bs[BN][TSTRA];

    const int m0  = blockIdx.x * BM;
    const int n0  = blockIdx.y * BN;
    const int tid = threadIdx.x;
    const int tn  = tid & 15;
    const int tm  = tid >> 4;

    unsigned long long acc[8][4];
#pragma unroll
    for (int i = 0; i < 8; i++)
#pragma unroll
        for (int j = 0; j < 4; j++) acc[i][j] = 0ull;

    const int ar = tid >> 3;
    const int ac = (tid & 7) * 4;

    for (int k0 = 0; k0 < I_; k0 += BK) {
#pragma unroll
        for (int p = 0; p < 4; p++) {
            int row = p * 32 + ar;
            float4 v = *(const float4*)(x + (size_t)(m0 + row) * I_ + k0 + ac);
            *(float4*)&As[row][ac] = v;
        }
#pragma unroll
        for (int p = 0; p < 2; p++) {
            int row = p * 32 + ar;
            int n = n0 + row;
            float4 v = make_float4(0.f, 0.f, 0.f, 0.f);
            if (n < H_) v = *(const float4*)(Wx + (size_t)n * I_ + k0 + ac);
            *(float4*)&Bs[row][ac] = v;
        }
        __syncthreads();

#pragma unroll
        for (int j = 0; j < BK / 4; j++) {
            ulonglong2 b[4];
#pragma unroll
            for (int nn = 0; nn < 4; nn++)
                b[nn] = *(const ulonglong2*)&Bs[tn * 4 + nn][4 * j];
#pragma unroll
            for (int mm = 0; mm < 8; mm++) {
                ulonglong2 a = *(const ulonglong2*)&As[tm * 8 + mm][4 * j];
#pragma unroll
                for (int nn = 0; nn < 4; nn++) {
                    acc[mm][nn] = fma2(a.x, b[nn].x, acc[mm][nn]);
                    acc[mm][nn] = fma2(a.y, b[nn].y, acc[mm][nn]);
                }
            }
        }
        __syncthreads();
    }

#pragma unroll
    for (int nn = 0; nn < 4; nn++) {
        int n = n0 + tn * 4 + nn;
        if (n >= H_) continue;
        float bias = bh[n];
#pragma unroll
        for (int mm = 0; mm < 8; mm++) {
            int m = m0 + tm * 8 + mm;
            float2 f = u2f2(acc[mm][nn]);
            out[(size_t)m * H_ + n] = f.x + f.y + bias;
        }
    }
}

// ---------------------------------------------------------------------------
// Kernel 2: recurrence, 2-CTA cluster k-split.
//   cluster = 8 batches. CTA rank r owns k in [125r, 125r+125):
//     - Wh[0:250, k-half] in smem (row stride 132 floats -> conflict-free)
//     - hp slice for its k-half only (padded to 128, zeros beyond 125)
//   Per step: each CTA computes partial dots for ALL 250 h over its k-half;
//   partials for the OTHER CTA's h-range are pushed into the peer's smem via
//   st.shared::cluster (double-buffered by t&1); one barrier.cluster; then
//   CTA r finalizes h in [125r, 125r+125): tanh(xp + own + peer partial),
//   stores to out and to its LOCAL hp slice (h-range == k-range, no hp
//   exchange needed).
// ---------------------------------------------------------------------------
#define KH    125          // k per CTA
#define KPAD  128          // padded k extent (zeros in [125,128))
#define WSTR2 132          // weight row stride floats (33 float4 granules, odd)
#define BT8   8            // batches per cluster

__global__ __launch_bounds__(256, 1) __cluster_dims__(2, 1, 1)
void rnn_rec2(const float* __restrict__ h0, const float* __restrict__ Wh,
              float* __restrict__ out)
{
    extern __shared__ float sm[];
    float* Wsm = sm;                          // 250 * 132
    float* hpB = sm + H_ * WSTR2;             // 8 * 128
    float* buf = hpB + BT8 * KPAD;            // 2 * 125 * 8 (peer-written)

    const int tid  = threadIdx.x;
    unsigned int rank;
    asm("mov.u32 %0, %%cluster_ctarank;" : "=r"(rank));
    const int b0 = (blockIdx.x >> 1) * BT8;   // cluster id * 8
    const int k0 = (int)rank * KH;            // this CTA's global k offset
    const int ok0 = KH - k0;                  // peer's k offset (125 or 0)

    // weights: row h, cols c in [0,KPAD), zero-padded beyond KH
    for (int idx = tid; idx < H_ * KPAD; idx += 256) {
        int r = idx >> 7;
        int c = idx & 127;
        Wsm[r * WSTR2 + c] = (c < KH) ? Wh[(size_t)r * H_ + k0 + c] : 0.f;
    }
    // hp slice init (this CTA's k-half), pads zeroed
    for (int idx = tid; idx < BT8 * KPAD; idx += 256) {
        int b = idx >> 7;
        int c = idx & 127;
        hpB[idx] = (c < KH) ? h0[(size_t)(b0 + b) * H_ + k0 + c] : 0.f;
    }
    __syncthreads();

    const bool rowact = (tid < H_);
    const bool fin    = rowact && (tid >= k0) && (tid < k0 + KH);
    const bool snd    = rowact && !fin;
    const float* wrow = Wsm + tid * WSTR2;

    // remote address of peer's buf (same smem offset, other rank)
    unsigned int buf_l = smem_u32(buf);
    unsigned int buf_r;
    asm("mapa.shared::cluster.u32 %0, %1, %2;"
        : "=r"(buf_r) : "r"(buf_l), "r"(1u - rank));
    // sender thread's slot byte offset in peer's buf: (tid - ok0)*32
    const unsigned int snd_off = (unsigned int)(tid - ok0) * 32u;

    for (int t = 0; t < T_; t++) {
        // prefetch xproj values for finalize threads (hide latency under dots)
        float xpv[BT8];
        if (fin) {
#pragma unroll
            for (int b = 0; b < BT8; b++)
                xpv[b] = out[((size_t)(b0 + b) * T_ + t) * H_ + tid];
        }

        // partial dot over this CTA's k-half, all 8 batches
        unsigned long long acc[BT8];
#pragma unroll
        for (int b = 0; b < BT8; b++) acc[b] = 0ull;
        if (rowact) {
#pragma unroll 4
            for (int j = 0; j < KPAD / 4; j++) {
                ulonglong2 w = *(const ulonglong2*)(wrow + 4 * j);
#pragma unroll
                for (int b = 0; b < BT8; b++) {
                    ulonglong2 p = *(const ulonglong2*)(hpB + b * KPAD + 4 * j);
                    acc[b] = fma2(w.x, p.x, acc[b]);
                    acc[b] = fma2(w.y, p.y, acc[b]);
                }
            }
        }
        float part[BT8];
#pragma unroll
        for (int b = 0; b < BT8; b++) {
            float2 f = u2f2(acc[b]);
            part[b] = f.x + f.y;
        }

        // ship partials for peer-owned h rows into peer's buf[t&1]
        if (snd) {
            unsigned int dst = buf_r + (unsigned int)(t & 1) * (KH * 32u) + snd_off;
            asm volatile("st.shared::cluster.v4.f32 [%0], {%1,%2,%3,%4};"
                         :: "r"(dst), "f"(part[0]), "f"(part[1]),
                            "f"(part[2]), "f"(part[3]) : "memory");
            asm volatile("st.shared::cluster.v4.f32 [%0], {%1,%2,%3,%4};"
                         :: "r"(dst + 16u), "f"(part[4]), "f"(part[5]),
                            "f"(part[6]), "f"(part[7]) : "memory");
        }

        // cluster barrier: peer partials visible; also orders prev-step hp
        // reads before this step's hp writes on the peer side
        asm volatile("barrier.cluster.arrive.aligned;" ::: "memory");
        asm volatile("barrier.cluster.wait.aligned;" ::: "memory");

        if (fin) {
            const float* pb = buf + (t & 1) * (KH * 8) + (tid - k0) * 8;
            float4 q0 = *(const float4*)(pb);
            float4 q1 = *(const float4*)(pb + 4);
            float v[BT8];
            v[0] = tanhf(xpv[0] + part[0] + q0.x);
            v[1] = tanhf(xpv[1] + part[1] + q0.y);
            v[2] = tanhf(xpv[2] + part[2] + q0.z);
            v[3] = tanhf(xpv[3] + part[3] + q0.w);
            v[4] = tanhf(xpv[4] + part[4] + q1.x);
            v[5] = tanhf(xpv[5] + part[5] + q1.y);
            v[6] = tanhf(xpv[6] + part[6] + q1.z);
            v[7] = tanhf(xpv[7] + part[7] + q1.w);
#pragma unroll
            for (int b = 0; b < BT8; b++)
                out[((size_t)(b0 + b) * T_ + t) * H_ + tid] = v[b];
#pragma unroll
            for (int b = 0; b < BT8; b++)
                hpB[b * KPAD + (tid - k0)] = v[b];
        }
        __syncthreads();   // hp writes visible to all warps before next step
    }
}

// ---------------------------------------------------------------------------
extern "C" void kernel_launch(void* const* d_in, const int* in_sizes, int n_in,
                              void* d_out, int out_size)
{
    const float* x  = (const float*)d_in[0];
    const float* h0 = (const float*)d_in[1];
    const float* Wx = (const float*)d_in[2];
    const float* Wh = (const float*)d_in[3];
    const float* bh = (const float*)d_in[4];
    float* out = (float*)d_out;

    static int attr_done = 0;
    size_t smem2 = (size_t)(H_ * WSTR2 + BT8 * KPAD + 2 * KH * 8) * sizeof(float);
    if (!attr_done) {
        cudaFuncSetAttribute(rnn_rec2,
                             cudaFuncAttributeMaxDynamicSharedMemorySize,
                             (int)smem2);
        attr_done = 1;
    }

    // 1) xproj + bias into d_out (scratch reuse, no allocation)
    dim3 g1((B_ * T_) / BM, (H_ + BN - 1) / BN);
    xproj_kernel<<<g1, 256>>>(x, Wx, bh, out);

    // 2) recurrence: 64 clusters x 2 CTAs, in-place on d_out
    rnn_rec2<<<(B_ / BT8) * 2, 256, smem2>>>(h0, Wh, out);
}